// round 5
// baseline (speedup 1.0000x reference)
#include <cuda_runtime.h>
#include <cstdint>

// ---------------- problem constants ----------------
#define Nn    20000
#define N1c   6000
#define N2c   6000
#define Rr    3
#define Ee    200000
#define HIDc  128
#define NDIMc 64
#define D1c   64
#define D2c   32
#define Sc    2

// ---------------- device scratch ----------------
__device__ int   g_deg[Rr * Nn];
__device__ int   g_cur[Rr * Nn];
__device__ int   g_ptr[Rr * (Nn + 1)];
__device__ int   g_csrc[Rr * Ee];
__device__ float g_h[(size_t)6 * Nn * 256];
__device__ float g_el[480000];
__device__ float g_er[480000];
__device__ float g_hid[3 * Nn * D1c];   // slots 0,1 = hidden1[s]; slot 2 = hiddenx

// ---------------- f32x2 helpers (attention) ----------------
__device__ __forceinline__ unsigned long long dup2(float a) {
    unsigned long long r;
    asm("mov.b64 %0, {%1, %1};" : "=l"(r) : "f"(a));
    return r;
}
__device__ __forceinline__ void ffma2(unsigned long long& d, unsigned long long a, unsigned long long b) {
    asm("fma.rn.f32x2 %0, %1, %2, %0;" : "+l"(d) : "l"(a), "l"(b));
}
__device__ __forceinline__ float2 unpk(unsigned long long v) {
    float2 f;
    asm("mov.b64 {%0, %1}, %2;" : "=f"(f.x), "=f"(f.y) : "l"(v));
    return f;
}

// ---------------- tf32 mma helpers ----------------
__device__ __forceinline__ uint32_t f2tf(float f) {
    uint32_t r;
    asm("cvt.rna.tf32.f32 %0, %1;" : "=r"(r) : "f"(f));
    return r;
}
__device__ __forceinline__ uint32_t sptr(const void* p) {
    return (uint32_t)__cvta_generic_to_shared(p);
}
__device__ __forceinline__ void ldsm_x4(uint32_t& r0, uint32_t& r1, uint32_t& r2, uint32_t& r3, uint32_t a) {
    asm volatile("ldmatrix.sync.aligned.m8n8.x4.shared.b16 {%0,%1,%2,%3}, [%4];"
                 : "=r"(r0), "=r"(r1), "=r"(r2), "=r"(r3) : "r"(a));
}
__device__ __forceinline__ void ldsm_x2(uint32_t& r0, uint32_t& r1, uint32_t a) {
    asm volatile("ldmatrix.sync.aligned.m8n8.x2.shared.b16 {%0,%1}, [%2];"
                 : "=r"(r0), "=r"(r1) : "r"(a));
}
__device__ __forceinline__ void mma_tf32(float c[4], const uint32_t a[4], const uint32_t b[2]) {
    asm volatile("mma.sync.aligned.m16n8k8.row.col.f32.tf32.tf32.f32 "
                 "{%0,%1,%2,%3},{%4,%5,%6,%7},{%8,%9},{%0,%1,%2,%3};"
                 : "+f"(c[0]), "+f"(c[1]), "+f"(c[2]), "+f"(c[3])
                 : "r"(a[0]), "r"(a[1]), "r"(a[2]), "r"(a[3]), "r"(b[0]), "r"(b[1]));
}

// ---------------- CSR build ----------------
__global__ void k_zero_deg() {
    int i = blockIdx.x * blockDim.x + threadIdx.x;
    if (i < Rr * Nn) g_deg[i] = 0;
}

__global__ void k_hist(const int* __restrict__ dst) {
    int idx = blockIdx.x * blockDim.x + threadIdx.x;
    if (idx < Rr * Ee) {
        int r = idx / Ee;
        atomicAdd(&g_deg[r * Nn + dst[idx]], 1);
    }
}

__global__ void k_scan() {
    __shared__ int sums[32];
    __shared__ int carry_s;
    int r = blockIdx.x;
    int t = threadIdx.x;
    int lane = t & 31, warp = t >> 5;
    if (t == 0) carry_s = 0;
    __syncthreads();
    for (int base = 0; base < Nn; base += 1024) {
        int carry = carry_s;
        int i = base + t;
        int v = (i < Nn) ? g_deg[r * Nn + i] : 0;
        int inc = v;
#pragma unroll
        for (int off = 1; off < 32; off <<= 1) {
            int n = __shfl_up_sync(0xffffffffu, inc, off);
            if (lane >= off) inc += n;
        }
        if (lane == 31) sums[warp] = inc;
        __syncthreads();
        if (warp == 0) {
            int s = sums[lane];
#pragma unroll
            for (int off = 1; off < 32; off <<= 1) {
                int n = __shfl_up_sync(0xffffffffu, s, off);
                if (lane >= off) s += n;
            }
            sums[lane] = s;
        }
        __syncthreads();
        int woff = (warp > 0) ? sums[warp - 1] : 0;
        int total = carry + woff + inc;
        if (i < Nn) {
            g_ptr[r * (Nn + 1) + i] = total - v;
            g_cur[r * Nn + i]       = total - v;
        }
        __syncthreads();
        if (t == 1023) carry_s = total;
        __syncthreads();
    }
    if (t == 0) g_ptr[r * (Nn + 1) + Nn] = carry_s;
}

__global__ void k_scatter(const int* __restrict__ src, const int* __restrict__ dst) {
    int idx = blockIdx.x * blockDim.x + threadIdx.x;
    if (idx < Rr * Ee) {
        int r = idx / Ee;
        int d = dst[idx];
        int pos = atomicAdd(&g_cur[r * Nn + d], 1);
        g_csrc[(size_t)r * Ee + pos] = src[idx];
    }
}

// ---------------- tf32 mma GEMM: C[z] = A[inst] @ B[inst,r], z = inst*Rr + r ----------------
// BM=128, BK=32, 256 threads (8 warps as 4m x 2n). BN = 128 or 64.
template<int BN>
__global__ __launch_bounds__(256) void gemm_mma(
    const float* __restrict__ Abase, size_t strideAinst, int K,
    const float* __restrict__ B0, const float* __restrict__ B1, const float* __restrict__ B2,
    int HF, float* __restrict__ Cbase, int M)
{
    constexpr int RS = 36;                 // row stride in floats (144B = 9 x 16B granules)
    constexpr int WN = BN / 2;
    constexpr int NT = WN / 8;
    __shared__ __align__(16) uint32_t As[128 * RS];
    __shared__ __align__(16) uint32_t Bs[BN * RS];

    int z = blockIdx.z;
    int r = z % Rr, inst = z / Rr;
    const float* A  = Abase + (size_t)inst * strideAinst;
    const float* Bw = (inst == 0 ? B0 : (inst == 1 ? B1 : B2)) + (size_t)r * K * HF;
    float* C = Cbase + (size_t)z * Nn * HF;

    int t = threadIdx.x;
    int lane = t & 31, warp = t >> 5;
    int warp_m = warp & 3, warp_n = warp >> 2;
    int bm = blockIdx.x * 128, bn = blockIdx.y * BN;

    float c[2][NT][4];
#pragma unroll
    for (int mt = 0; mt < 2; mt++)
#pragma unroll
        for (int nt = 0; nt < NT; nt++)
#pragma unroll
            for (int q = 0; q < 4; q++) c[mt][nt][q] = 0.f;

    for (int k0 = 0; k0 < K; k0 += 32) {
        // A tile: 128x32 -> 4 float4 per thread
#pragma unroll
        for (int p = 0; p < 4; p++) {
            int fid = p * 256 + t;
            int row = fid >> 3, g = fid & 7;
            float4 v = make_float4(0.f, 0.f, 0.f, 0.f);
            if (bm + row < M)
                v = *reinterpret_cast<const float4*>(A + (size_t)(bm + row) * K + k0 + g * 4);
            uint32_t* d = &As[row * RS + g * 4];
            d[0] = f2tf(v.x); d[1] = f2tf(v.y); d[2] = f2tf(v.z); d[3] = f2tf(v.w);
        }
        // B tile: 32 x BN, stored transposed [n][k]  (BN*32/1024 = BN/32 passes)
#pragma unroll
        for (int p = 0; p < BN / 32; p++) {
            int fid = p * 256 + t;
            int k = fid / (BN / 4), n = (fid % (BN / 4)) * 4;
            float4 v = *reinterpret_cast<const float4*>(Bw + (size_t)(k0 + k) * HF + bn + n);
            Bs[(n + 0) * RS + k] = f2tf(v.x);
            Bs[(n + 1) * RS + k] = f2tf(v.y);
            Bs[(n + 2) * RS + k] = f2tf(v.z);
            Bs[(n + 3) * RS + k] = f2tf(v.w);
        }
        __syncthreads();
#pragma unroll
        for (int ks = 0; ks < 4; ks++) {
            uint32_t a[2][4];
#pragma unroll
            for (int mt = 0; mt < 2; mt++) {
                int rr = warp_m * 32 + mt * 16 + (lane & 7) + ((lane >> 3) & 1) * 8;
                int gg = ks * 2 + (lane >> 4);
                ldsm_x4(a[mt][0], a[mt][1], a[mt][2], a[mt][3], sptr(&As[rr * RS + gg * 4]));
            }
            uint32_t b[NT][2];
#pragma unroll
            for (int nt = 0; nt < NT; nt++) {
                int rB = warp_n * WN + nt * 8 + (lane & 7);
                int gB = ks * 2 + ((lane >> 3) & 1);
                ldsm_x2(b[nt][0], b[nt][1], sptr(&Bs[rB * RS + gB * 4]));
            }
#pragma unroll
            for (int mt = 0; mt < 2; mt++)
#pragma unroll
                for (int nt = 0; nt < NT; nt++) mma_tf32(c[mt][nt], a[mt], b[nt]);
        }
        __syncthreads();
    }

#pragma unroll
    for (int mt = 0; mt < 2; mt++)
#pragma unroll
        for (int nt = 0; nt < NT; nt++) {
            int row0 = bm + warp_m * 32 + mt * 16 + (lane >> 2);
            int col  = bn + warp_n * WN + nt * 8 + (lane & 3) * 2;
            if (row0 < M)
                *reinterpret_cast<float2*>(C + (size_t)row0 * HF + col) = make_float2(c[mt][nt][0], c[mt][nt][1]);
            if (row0 + 8 < M)
                *reinterpret_cast<float2*>(C + (size_t)(row0 + 8) * HF + col) = make_float2(c[mt][nt][2], c[mt][nt][3]);
        }
}

// ---------------- el/er projections: warp per (inst, relation, node) ----------------
template <int H, int F>
__global__ void k_elr(const float* __restrict__ hb,
                      const float* __restrict__ al0, const float* __restrict__ al1, const float* __restrict__ al2,
                      const float* __restrict__ ar0, const float* __restrict__ ar1, const float* __restrict__ ar2,
                      float* __restrict__ el, float* __restrict__ er, int nInst)
{
    const int HF = H * F, PL = HF / 32, LPH = 32 / H;
    int w    = (blockIdx.x * blockDim.x + threadIdx.x) >> 5;
    int lane = threadIdx.x & 31;
    if (w >= nInst * Rr * Nn) return;
    int zr = w / Nn;
    int inst = zr / Rr, r = zr % Rr;
    const float* al = (inst == 0 ? al0 : (inst == 1 ? al1 : al2));
    const float* ar = (inst == 0 ? ar0 : (inst == 1 ? ar1 : ar2));
    const float* hp  = hb + (size_t)w * HF + lane * PL;
    const float* alp = al + (size_t)r * HF + lane * PL;
    const float* arp = ar + (size_t)r * HF + lane * PL;
    float sl = 0.f, sr = 0.f;
#pragma unroll
    for (int k = 0; k < PL; k++) {
        float hv = hp[k];
        sl += hv * alp[k];
        sr += hv * arp[k];
    }
#pragma unroll
    for (int off = 1; off < LPH; off <<= 1) {
        sl += __shfl_xor_sync(0xffffffffu, sl, off);
        sr += __shfl_xor_sync(0xffffffffu, sr, off);
    }
    if ((lane & (LPH - 1)) == 0) {
        int hh = lane / LPH;
        el[(size_t)w * H + hh] = sl;
        er[(size_t)w * H + hh] = sr;
    }
}

// ---------------- attention: warp per dst node, online softmax, batched over instances ----------------
__device__ __forceinline__ float leaky(float e) { return (e > 0.f) ? e : 0.2f * e; }

template <int H, int F, bool RELU, bool ADD>
__global__ void k_attn(const float* __restrict__ hb, const float* __restrict__ elb,
                       const float* __restrict__ erb, float* __restrict__ outb,
                       long long outStride, const float* __restrict__ resid, int instBase)
{
    constexpr int HF = H * F, PL = HF / 32, LPH = 32 / H, PU = PL / 2;
    int inst = blockIdx.y + instBase;
    const float* hbi = hb  + (size_t)inst * Rr * Nn * HF;
    const float* el  = elb + (size_t)inst * Rr * Nn * H;
    const float* er  = erb + (size_t)inst * Rr * Nn * H;
    float* out = outb + (size_t)inst * outStride;

    int w    = (blockIdx.x * blockDim.x + threadIdx.x) >> 5;
    int lane = threadIdx.x & 31;
    if (w >= Nn) return;
    const int i    = w;
    const int hidx = (lane * PL) / F;
    unsigned long long accA[PU], accB[PU];
#pragma unroll
    for (int k = 0; k < PU; k++) { accA[k] = 0ull; accB[k] = 0ull; }

    for (int r = 0; r < Rr; r++) {
        int s0 = g_ptr[r * (Nn + 1) + i];
        int s1 = g_ptr[r * (Nn + 1) + i + 1];
        if (s0 == s1) continue;
        float eri[H];
        if (H == 4) {
            float4 v = *reinterpret_cast<const float4*>(er + (size_t)(r * Nn + i) * 4);
            eri[0] = v.x; eri[1 % H] = v.y; eri[2 % H] = v.z; eri[3 % H] = v.w;
        } else {
            float2 v = *reinterpret_cast<const float2*>(er + (size_t)(r * Nn + i) * 2);
            eri[0] = v.x; eri[1 % H] = v.y;
        }

        // ---- single-pass online softmax (max + denom fused) ----
        float m[H], d[H];
#pragma unroll
        for (int hh = 0; hh < H; hh++) { m[hh] = -1e30f; d[hh] = 0.f; }
        for (int j = s0 + lane; j < s1; j += 32) {
            int sn = g_csrc[(size_t)r * Ee + j];
            float ev[H];
            if (H == 4) {
                float4 v = *reinterpret_cast<const float4*>(el + (size_t)(r * Nn + sn) * 4);
                ev[0] = v.x; ev[1 % H] = v.y; ev[2 % H] = v.z; ev[3 % H] = v.w;
            } else {
                float2 v = *reinterpret_cast<const float2*>(el + (size_t)(r * Nn + sn) * 2);
                ev[0] = v.x; ev[1 % H] = v.y;
            }
#pragma unroll
            for (int hh = 0; hh < H; hh++) {
                float e = leaky(ev[hh] + eri[hh]);
                float mn = fmaxf(m[hh], e);
                float sc = __expf(fminf(m[hh], e) - mn);
                d[hh] = (e > m[hh]) ? fmaf(d[hh], sc, 1.f) : (d[hh] + sc);
                m[hh] = mn;
            }
        }
#pragma unroll
        for (int off = 16; off > 0; off >>= 1) {
#pragma unroll
            for (int hh = 0; hh < H; hh++) {
                float m2 = __shfl_xor_sync(0xffffffffu, m[hh], off);
                float d2 = __shfl_xor_sync(0xffffffffu, d[hh], off);
                float mn = fmaxf(m[hh], m2);
                d[hh] = d[hh] * __expf(m[hh] - mn) + d2 * __expf(m2 - mn);
                m[hh] = mn;
            }
        }
        float inv[H];
#pragma unroll
        for (int hh = 0; hh < H; hh++) inv[hh] = 1.f / (d[hh] + 1e-16f);

        // ---- weighted gather, unrolled x2 with dual accumulators ----
        float mi = m[hidx], ivi = inv[hidx], ei = eri[hidx];
        int j = s0;
        for (; j + 1 < s1; j += 2) {
            int sn0 = g_csrc[(size_t)r * Ee + j];
            int sn1 = g_csrc[(size_t)r * Ee + j + 1];
            float e0 = leaky(el[(size_t)(r * Nn + sn0) * H + hidx] + ei);
            float e1 = leaky(el[(size_t)(r * Nn + sn1) * H + hidx] + ei);
            float a0 = __expf(e0 - mi) * ivi;
            float a1 = __expf(e1 - mi) * ivi;
            unsigned long long ad0 = dup2(a0), ad1 = dup2(a1);
            const float* h0 = hbi + (size_t)(r * Nn + sn0) * HF + lane * PL;
            const float* h1 = hbi + (size_t)(r * Nn + sn1) * HF + lane * PL;
            if (PU == 4) {
                const ulonglong2* p0 = reinterpret_cast<const ulonglong2*>(h0);
                const ulonglong2* p1 = reinterpret_cast<const ulonglong2*>(h1);
                ulonglong2 u0 = p0[0], u1 = p0[1];
                ulonglong2 v0 = p1[0], v1 = p1[1];
                ffma2(accA[0], ad0, u0.x); ffma2(accA[1 % PU], ad0, u0.y);
                ffma2(accA[2 % PU], ad0, u1.x); ffma2(accA[3 % PU], ad0, u1.y);
                ffma2(accB[0], ad1, v0.x); ffma2(accB[1 % PU], ad1, v0.y);
                ffma2(accB[2 % PU], ad1, v1.x); ffma2(accB[3 % PU], ad1, v1.y);
            } else {
                unsigned long long u = *reinterpret_cast<const unsigned long long*>(h0);
                unsigned long long v = *reinterpret_cast<const unsigned long long*>(h1);
                ffma2(accA[0], ad0, u);
                ffma2(accB[0], ad1, v);
            }
        }
        if (j < s1) {
            int sn0 = g_csrc[(size_t)r * Ee + j];
            float e0 = leaky(el[(size_t)(r * Nn + sn0) * H + hidx] + ei);
            float a0 = __expf(e0 - mi) * ivi;
            unsigned long long ad0 = dup2(a0);
            const float* h0 = hbi + (size_t)(r * Nn + sn0) * HF + lane * PL;
            if (PU == 4) {
                const ulonglong2* p0 = reinterpret_cast<const ulonglong2*>(h0);
                ulonglong2 u0 = p0[0], u1 = p0[1];
                ffma2(accA[0], ad0, u0.x); ffma2(accA[1 % PU], ad0, u0.y);
                ffma2(accA[2 % PU], ad0, u1.x); ffma2(accA[3 % PU], ad0, u1.y);
            } else {
                unsigned long long u = *reinterpret_cast<const unsigned long long*>(h0);
                ffma2(accA[0], ad0, u);
            }
        }
    }

    // merge dual accumulators, mean over heads + activation + write
    float af[PL];
#pragma unroll
    for (int u = 0; u < PU; u++) {
        float2 fa = unpk(accA[u]);
        float2 fb = unpk(accB[u]);
        af[2 * u] = fa.x + fb.x; af[2 * u + 1] = fa.y + fb.y;
    }
#pragma unroll
    for (int k = 0; k < PL; k++) {
        float v = af[k];
#pragma unroll
        for (int off = LPH; off < 32; off <<= 1)
            v += __shfl_xor_sync(0xffffffffu, v, off);
        v *= (1.0f / H);
        if (RELU) v = fmaxf(v, 0.f);
        if (lane < LPH) {
            int idx = i * F + lane * PL + k;
            if (ADD) v += resid[idx];
            out[idx] = v;
        }
    }
}

// ---------------- misc ----------------
__global__ void k_rk2(const float* __restrict__ rk, float* __restrict__ out) {
    int i = threadIdx.x;
    if (i < 32) out[i] = 1.f / (1.f + __expf(-rk[i]));
}

__device__ __forceinline__ float sigf(float x) { return 1.f / (1.f + __expf(-x)); }

// ---------------- adj = mean_s sigmoid(z1[s] @ z2[s]^T), tf32 mma, 64x64 tile ----------------
__global__ __launch_bounds__(256) void k_adj_mma(const float* __restrict__ mu, float* __restrict__ adj)
{
    constexpr int RS = 36;
    __shared__ __align__(16) uint32_t Z1s[Sc][64 * RS];
    __shared__ __align__(16) uint32_t Z2s[Sc][64 * RS];
    int t = threadIdx.x;
    int lane = t & 31, warp = t >> 5;
    int warp_m = warp & 1, warp_n = warp >> 1;   // 2m x 4n; WM=32, WN=16, MT=2, NT=2
    int bi = blockIdx.x * 64, bj = blockIdx.y * 64;

#pragma unroll
    for (int s = 0; s < Sc; s++) {
#pragma unroll
        for (int p = 0; p < 2; p++) {
            int fid = p * 256 + t;
            int row = fid >> 3, g = fid & 7;
            float4 v = make_float4(0.f, 0.f, 0.f, 0.f);
            if (bi + row < N1c)
                v = *reinterpret_cast<const float4*>(mu + ((size_t)s * Nn + bi + row) * 32 + g * 4);
            uint32_t* d = &Z1s[s][row * RS + g * 4];
            d[0] = f2tf(v.x); d[1] = f2tf(v.y); d[2] = f2tf(v.z); d[3] = f2tf(v.w);
            v = make_float4(0.f, 0.f, 0.f, 0.f);
            if (bj + row < N2c)
                v = *reinterpret_cast<const float4*>(mu + ((size_t)s * Nn + N1c + bj + row) * 32 + g * 4);
            d = &Z2s[s][row * RS + g * 4];
            d[0] = f2tf(v.x); d[1] = f2tf(v.y); d[2] = f2tf(v.z); d[3] = f2tf(v.w);
        }
    }
    __syncthreads();

    float c[Sc][2][2][4];
#pragma unroll
    for (int s = 0; s < Sc; s++)
#pragma unroll
        for (int mt = 0; mt < 2; mt++)
#pragma unroll
            for (int nt = 0; nt < 2; nt++)
#pragma unroll
                for (int q = 0; q < 4; q++) c[s][mt][nt][q] = 0.f;

#pragma unroll
    for (int ks = 0; ks < 4; ks++) {
#pragma unroll
        for (int s = 0; s < Sc; s++) {
            uint32_t a[2][4];
#pragma unroll
            for (int mt = 0; mt < 2; mt++) {
                int rr = warp_m * 32 + mt * 16 + (lane & 7) + ((lane >> 3) & 1) * 8;
                int gg = ks * 2 + (lane >> 4);
                ldsm_x4(a[mt][0], a[mt][1], a[mt][2], a[mt][3], sptr(&Z1s[s][rr * RS + gg * 4]));
            }
            uint32_t b[2][2];
#pragma unroll
            for (int nt = 0; nt < 2; nt++) {
                int rB = warp_n * 16 + nt * 8 + (lane & 7);
                int gB = ks * 2 + ((lane >> 3) & 1);
                ldsm_x2(b[nt][0], b[nt][1], sptr(&Z2s[s][rB * RS + gB * 4]));
            }
#pragma unroll
            for (int mt = 0; mt < 2; mt++)
#pragma unroll
                for (int nt = 0; nt < 2; nt++) mma_tf32(c[s][mt][nt], a[mt], b[nt]);
        }
    }

#pragma unroll
    for (int mt = 0; mt < 2; mt++)
#pragma unroll
        for (int nt = 0; nt < 2; nt++) {
            int row0 = bi + warp_m * 32 + mt * 16 + (lane >> 2);
            int col  = bj + warp_n * 16 + nt * 8 + (lane & 3) * 2;
            if (col >= N2c) continue;
            if (row0 < N1c) {
                float2 v = make_float2(0.5f * (sigf(c[0][mt][nt][0]) + sigf(c[1][mt][nt][0])),
                                       0.5f * (sigf(c[0][mt][nt][1]) + sigf(c[1][mt][nt][1])));
                *reinterpret_cast<float2*>(adj + (size_t)row0 * N2c + col) = v;
            }
            if (row0 + 8 < N1c) {
                float2 v = make_float2(0.5f * (sigf(c[0][mt][nt][2]) + sigf(c[1][mt][nt][2])),
                                       0.5f * (sigf(c[0][mt][nt][3]) + sigf(c[1][mt][nt][3])));
                *reinterpret_cast<float2*>(adj + (size_t)(row0 + 8) * N2c + col) = v;
            }
        }
}

// ---------------- host-side orchestration ----------------
extern "C" void kernel_launch(void* const* d_in, const int* in_sizes, int n_in,
                              void* d_out, int out_size)
{
    (void)in_sizes; (void)n_in; (void)out_size;
    const float* x     = (const float*)d_in[0];
    const float* noise = (const float*)d_in[1];
    const float* W1    = (const float*)d_in[2];
    const float* al1   = (const float*)d_in[3];
    const float* ar1   = (const float*)d_in[4];
    const float* We    = (const float*)d_in[5];
    const float* ale   = (const float*)d_in[6];
    const float* are   = (const float*)d_in[7];
    const float* W2    = (const float*)d_in[8];
    const float* al2   = (const float*)d_in[9];
    const float* ar2   = (const float*)d_in[10];
    const float* W3    = (const float*)d_in[11];
    const float* al3   = (const float*)d_in[12];
    const float* ar3   = (const float*)d_in[13];
    const float* rk    = (const float*)d_in[14];
    const int*   src   = (const int*)d_in[15];
    const int*   dst   = (const int*)d_in[16];

    float* out     = (float*)d_out;
    float* out_adj = out;
    float* out_mu  = out + (size_t)N1c * N2c;
    float* out_lv  = out_mu + (size_t)Sc * Nn * D2c;
    float* out_rk  = out_lv + (size_t)Nn * D2c;

    float *hbuf, *elbuf, *erbuf, *hid;
    cudaGetSymbolAddress((void**)&hbuf,  g_h);
    cudaGetSymbolAddress((void**)&elbuf, g_el);
    cudaGetSymbolAddress((void**)&erbuf, g_er);
    cudaGetSymbolAddress((void**)&hid,   g_hid);
    float* hx = hid + (size_t)2 * Nn * D1c;

    // ---- CSR (shared by all 6 rgat layers) ----
    k_zero_deg<<<(Rr * Nn + 255) / 256, 256>>>();
    k_hist<<<(Rr * Ee + 255) / 256, 256>>>(dst);
    k_scan<<<Rr, 1024>>>();
    k_scatter<<<(Rr * Ee + 255) / 256, 256>>>(src, dst);

    // ---- layer x: hiddenx = rgat(x, W1, relu) ----
    gemm_mma<128><<<dim3(157, 2, 3), 256>>>(x, 0, HIDc, W1, W1, W1, 256, hbuf, Nn);
    k_elr<4, 64><<<(1 * Rr * Nn * 32 + 255) / 256, 256>>>(hbuf, al1, al1, al1, ar1, ar1, ar1, elbuf, erbuf, 1);
    k_attn<4, 64, true, false><<<dim3((Nn + 7) / 8, 1), 256>>>(hbuf, elbuf, erbuf, hx, 0, nullptr, 0);

    // ---- noise layers: hidden1[s] = hiddenx + rgat(noise[s], We, relu) ----
    gemm_mma<128><<<dim3(157, 2, 6), 256>>>(noise, (size_t)Nn * NDIMc, NDIMc, We, We, We, 256, hbuf, Nn);
    k_elr<4, 64><<<(2 * Rr * Nn * 32 + 255) / 256, 256>>>(hbuf, ale, ale, ale, are, are, are, elbuf, erbuf, 2);
    k_attn<4, 64, true, true><<<dim3((Nn + 7) / 8, 2), 256>>>(hbuf, elbuf, erbuf, hid, (long long)Nn * D1c, hx, 0);

    // ---- mu[0], mu[1], logvar: batched ----
    gemm_mma<64><<<dim3(157, 1, 9), 256>>>(hid, (size_t)Nn * D1c, D1c, W2, W2, W3, 64, hbuf, Nn);
    k_elr<2, 32><<<(3 * Rr * Nn * 32 + 255) / 256, 256>>>(hbuf, al2, al2, al3, ar2, ar2, ar3, elbuf, erbuf, 3);
    k_attn<2, 32, false, false><<<dim3((Nn + 7) / 8, 3), 256>>>(hbuf, elbuf, erbuf, out_mu, (long long)Nn * D2c, nullptr, 0);

    // ---- rk2 = sigmoid(rk_lgt) ----
    k_rk2<<<1, 32>>>(rk, out_rk);

    // ---- adj = mean_s sigmoid(z1[s] @ z2[s]^T) ----
    k_adj_mma<<<dim3((N1c + 63) / 64, (N2c + 63) / 64), 256>>>(out_mu, out_adj);
}